// round 11
// baseline (speedup 1.0000x reference)
#include <cuda_runtime.h>
#include <cstdint>
#include <cstddef>

// Problem constants
#define BATCH 64
#define TT    512
#define HID   512
#define G4    2048          // 4*HID
#define CTX   792
#define IND   1048
#define VOCAB 260
#define BCL   8
#define BED   32

// ---------------- static device scratch (no runtime allocation) ----------------
__device__ float g_ctxT[CTX * BATCH];                 // context transposed [k][b]
__device__ float g_ctxg[G4 * BATCH];                  // W_ih0[:, :792]@ctx + b_ih0 + b_hh0, [row][b]
__device__ float g_proj[(size_t)BCL * G4 * VOCAB];    // [j][row][v]  (17 MB)
__device__ float g_gx[(size_t)TT * G4 * BATCH];       // input gates [t][row][b] (268 MB, reused for both layers)
__device__ float g_h[(size_t)TT * HID * BATCH];       // h states [t][j][b] (64 MB, reused layer0 -> layer1)
__device__ float g_WoutT[HID * 256];                  // W_out transposed [k][v]
__device__ volatile unsigned g_bar;                   // grid barrier counter

// ---------------- math helpers ----------------
__device__ __forceinline__ float sigm(float x) { return 1.0f / (1.0f + __expf(-x)); }
__device__ __forceinline__ float tanh_(float x) { return 2.0f / (1.0f + __expf(-2.0f * x)) - 1.0f; }

// ---------------- 1) build transposed context [792][64] ----------------
__global__ __launch_bounds__(256) void build_ctx(
    const float* __restrict__ ecc,    // [64][512]
    const int*   __restrict__ cat,    // [64][3]
    const float* __restrict__ num,    // [64][16]
    const float* __restrict__ e0,     // [10][50]
    const float* __restrict__ e1,     // [128][64]
    const float* __restrict__ e2)     // [300][150]
{
    int idx = blockIdx.x * blockDim.x + threadIdx.x;   // 792*64 = 50688 exactly
    if (idx >= CTX * BATCH) return;
    int k = idx >> 6;
    int b = idx & 63;
    float v;
    if (k < 512)      v = ecc[b * 512 + k];
    else if (k < 562) v = e0[cat[b * 3 + 0] * 50  + (k - 512)];
    else if (k < 626) v = e1[cat[b * 3 + 1] * 64  + (k - 562)];
    else if (k < 776) v = e2[cat[b * 3 + 2] * 150 + (k - 626)];
    else              v = num[b * 16 + (k - 776)];
    g_ctxT[k * BATCH + b] = v;
}

// ---------------- 2) ctx gates: [2048][64] = W_ih0[:, :792] @ ctx + biases ----------------
__global__ __launch_bounds__(256) void ctx_gates_k(
    const float* __restrict__ Wih0, const float* __restrict__ bih0, const float* __restrict__ bhh0)
{
    int tid = threadIdx.x;
    int b = tid & 63, q = tid >> 6;
    int rbase = blockIdx.x * 32 + q * 8;   // 64 blocks * 32 rows
    float acc[8];
#pragma unroll
    for (int i = 0; i < 8; i++) acc[i] = bih0[rbase + i] + bhh0[rbase + i];
    for (int k = 0; k < CTX; k += 4) {
        float h0 = g_ctxT[(k + 0) * BATCH + b];
        float h1 = g_ctxT[(k + 1) * BATCH + b];
        float h2 = g_ctxT[(k + 2) * BATCH + b];
        float h3 = g_ctxT[(k + 3) * BATCH + b];
#pragma unroll
        for (int i = 0; i < 8; i++) {
            float4 w = *(const float4*)&Wih0[(size_t)(rbase + i) * IND + k];
            acc[i] += w.x * h0 + w.y * h1 + w.z * h2 + w.w * h3;
        }
    }
#pragma unroll
    for (int i = 0; i < 8; i++) g_ctxg[(rbase + i) * BATCH + b] = acc[i];
}

// ---------------- 3) proj[j][row][v] = W_ih0[row, 792+32j : +32] @ byte_emb[v] ----------------
__global__ __launch_bounds__(256) void proj_k(
    const float* __restrict__ Wih0, const float* __restrict__ bemb)
{
    __shared__ float emb_s[VOCAB * 33];   // padded stride 33 -> conflict-free
    __shared__ float Wc[8 * 32];
    int tid = threadIdx.x;
    int rowbase = blockIdx.x * 8;   // 256 row-tiles
    int j = blockIdx.y;             // 8
    for (int i = tid; i < VOCAB * BED; i += 256) {
        int v = i >> 5, k = i & 31;
        emb_s[v * 33 + k] = bemb[i];
    }
    if (tid < 256) {
        int r = tid >> 5, k = tid & 31;
        Wc[tid] = Wih0[(size_t)(rowbase + r) * IND + CTX + 32 * j + k];
    }
    __syncthreads();
    for (int v = tid; v < VOCAB; v += 256) {
#pragma unroll
        for (int r = 0; r < 8; r++) {
            float a = 0.f;
#pragma unroll
            for (int k = 0; k < 32; k++) a += Wc[r * 32 + k] * emb_s[v * 33 + k];
            g_proj[((size_t)j * G4 + rowbase + r) * VOCAB + v] = a;
        }
    }
}

// ---------------- 4) assemble gx0[t][row][b] ----------------
__global__ __launch_bounds__(256) void gx0_assemble(const int* __restrict__ payload)
{
    int t = blockIdx.y;
    int rowTile = blockIdx.x;   // 32 tiles of 64 rows
    __shared__ int sb[BATCH * BCL];
    int tid = threadIdx.x;
    for (int idx = tid; idx < BATCH * BCL; idx += 256) {
        int bb = idx >> 3, j = idx & 7;
        int p = t + j;
        int v = (p < 7) ? 256 : ((p == 7) ? 257 : payload[bb * TT + p - 8]);
        sb[idx] = v;
    }
    __syncthreads();
    int b = tid & 63, rq = tid >> 6;
    int vb[8];
#pragma unroll
    for (int j = 0; j < 8; j++) vb[j] = sb[b * 8 + j];
    int rbase = rowTile * 64 + rq * 16;
    for (int rr = 0; rr < 16; rr++) {
        int row = rbase + rr;
        float acc = g_ctxg[row * BATCH + b];
#pragma unroll
        for (int j = 0; j < 8; j++)
            acc += __ldg(&g_proj[((size_t)j * G4 + row) * VOCAB + vb[j]]);
        g_gx[(size_t)t * (G4 * BATCH) + row * BATCH + b] = acc;
    }
}

// ---------------- 5) barrier reset ----------------
__global__ void reset_bar_k() { g_bar = 0u; }

// ---------------- 6) persistent LSTM recurrence: one launch = 512 steps ----------------
// grid 128, block 256. All blocks co-resident (<=148 SMs). Block covers 4 hidden
// units x 64 batches; thread = 1 hidden unit x 1 batch (all 4 gates). Whh staged
// into smem ONCE; cell state kept in a register; grid-wide software barrier per step.
__global__ __launch_bounds__(256) void lstm_seq(const float* __restrict__ Whh)
{
    __shared__ float Ws[16 * HID];   // 16 gate-rows x 512 = 32 KB
    int tid = threadIdx.x;
    int b = tid & 63, q = tid >> 6;
    int j = blockIdx.x * 4 + q;

    // stage W rows {gate*512 + blockIdx.x*4 + qq} into smem (once per launch)
    for (int f = tid; f < 2048; f += 256) {          // 2048 float4 = 8192 floats
        int r16 = f >> 7;                             // 0..15
        int kk = (f & 127) * 4;
        int gate = r16 >> 2, qq = r16 & 3;
        *(float4*)&Ws[r16 * HID + kk] =
            *(const float4*)&Whh[(size_t)(gate * HID + blockIdx.x * 4 + qq) * HID + kk];
    }
    __syncthreads();

    const float* Wi = &Ws[(0 * 4 + q) * HID];
    const float* Wf = &Ws[(1 * 4 + q) * HID];
    const float* Wg = &Ws[(2 * 4 + q) * HID];
    const float* Wo = &Ws[(3 * 4 + q) * HID];

    float c = 0.f;

    for (int t = 0; t < TT; t++) {
        // input-gate contributions (issued early to overlap DRAM latency)
        size_t gxb = (size_t)t * (G4 * BATCH);
        float gi = __ldg(&g_gx[gxb + (0 * HID + j) * BATCH + b]);
        float gf = __ldg(&g_gx[gxb + (1 * HID + j) * BATCH + b]);
        float gg = __ldg(&g_gx[gxb + (2 * HID + j) * BATCH + b]);
        float go = __ldg(&g_gx[gxb + (3 * HID + j) * BATCH + b]);

        if (t > 0) {
            const float* hprev = g_h + (size_t)(t - 1) * (HID * BATCH);
            float ai = 0.f, af = 0.f, ag = 0.f, ao = 0.f;
#pragma unroll 2
            for (int k = 0; k < HID; k += 4) {
                float h0 = __ldg(&hprev[(k + 0) * BATCH + b]);
                float h1 = __ldg(&hprev[(k + 1) * BATCH + b]);
                float h2 = __ldg(&hprev[(k + 2) * BATCH + b]);
                float h3 = __ldg(&hprev[(k + 3) * BATCH + b]);
                float4 wi = *(const float4*)&Wi[k];
                float4 wf = *(const float4*)&Wf[k];
                float4 wg = *(const float4*)&Wg[k];
                float4 wo = *(const float4*)&Wo[k];
                ai += wi.x * h0 + wi.y * h1 + wi.z * h2 + wi.w * h3;
                af += wf.x * h0 + wf.y * h1 + wf.z * h2 + wf.w * h3;
                ag += wg.x * h0 + wg.y * h1 + wg.z * h2 + wg.w * h3;
                ao += wo.x * h0 + wo.y * h1 + wo.z * h2 + wo.w * h3;
            }
            gi += ai; gf += af; gg += ag; go += ao;
        }

        float si = sigm(gi), sf = sigm(gf), so = sigm(go);
        float tg = tanh_(gg);
        c = sf * c + si * tg;
        float h = so * tanh_(c);
        g_h[(size_t)t * (HID * BATCH) + j * BATCH + b] = h;

        if (t < TT - 1) {
            __threadfence();          // release: h_t visible before arrive
            __syncthreads();
            if (tid == 0) {
                atomicAdd((unsigned*)&g_bar, 1u);
                unsigned target = (unsigned)(t + 1) * (unsigned)gridDim.x;
                while (g_bar < target) { }   // volatile spin
                __threadfence();      // acquire before block proceeds
            }
            __syncthreads();
        }
    }
}

// ---------------- 7) gx1[t][row][b] = W_ih1 @ h1[t] + (b_ih1 + b_hh1) ----------------
__global__ __launch_bounds__(256) void gx1_k(
    const float* __restrict__ Wih1, const float* __restrict__ bih1, const float* __restrict__ bhh1)
{
    int t = blockIdx.y;
    int tile = blockIdx.x;     // 64 tiles * 32 rows
    int tid = threadIdx.x;
    int b = tid & 63, q = tid >> 6;
    int rbase = tile * 32 + q * 8;
    const float* ht = g_h + (size_t)t * (HID * BATCH);
    float acc[8];
#pragma unroll
    for (int i = 0; i < 8; i++) acc[i] = bih1[rbase + i] + bhh1[rbase + i];
    for (int k = 0; k < HID; k += 4) {
        float h0 = __ldg(&ht[(k + 0) * BATCH + b]);
        float h1 = __ldg(&ht[(k + 1) * BATCH + b]);
        float h2 = __ldg(&ht[(k + 2) * BATCH + b]);
        float h3 = __ldg(&ht[(k + 3) * BATCH + b]);
#pragma unroll
        for (int i = 0; i < 8; i++) {
            float4 w = *(const float4*)&Wih1[(size_t)(rbase + i) * HID + k];
            acc[i] += w.x * h0 + w.y * h1 + w.z * h2 + w.w * h3;
        }
    }
#pragma unroll
    for (int i = 0; i < 8; i++)
        g_gx[(size_t)t * (G4 * BATCH) + (rbase + i) * BATCH + b] = acc[i];
}

// ---------------- 8) transpose W_out [256][512] -> [512][256] ----------------
__global__ void transpose_wout(const float* __restrict__ W)
{
    __shared__ float tile[32][33];
    int bx = blockIdx.x;   // 16 k-tiles
    int by = blockIdx.y;   // 8 v-tiles
    int x = bx * 32 + threadIdx.x;  // k
    int y = by * 32 + threadIdx.y;  // v
    tile[threadIdx.y][threadIdx.x] = W[y * 512 + x];
    __syncthreads();
    g_WoutT[(bx * 32 + threadIdx.y) * 256 + by * 32 + threadIdx.x] = tile[threadIdx.x][threadIdx.y];
}

// ---------------- 9) output projection: logits[b][t][v] ----------------
__global__ __launch_bounds__(256) void out_k(const float* __restrict__ bout, float* __restrict__ out)
{
    int t = blockIdx.x;
    int v = threadIdx.x;     // 256
    const float* ht = g_h + (size_t)t * (HID * BATCH);
    float acc[64];
#pragma unroll
    for (int i = 0; i < 64; i++) acc[i] = 0.f;
    for (int k = 0; k < HID; k++) {
        float w = __ldg(&g_WoutT[k * 256 + v]);
        const float4* h4p = (const float4*)&ht[k * BATCH];
#pragma unroll
        for (int bb = 0; bb < 16; bb++) {
            float4 h4 = __ldg(&h4p[bb]);
            acc[bb * 4 + 0] += w * h4.x;
            acc[bb * 4 + 1] += w * h4.y;
            acc[bb * 4 + 2] += w * h4.z;
            acc[bb * 4 + 3] += w * h4.w;
        }
    }
    float bo = bout[v];
#pragma unroll
    for (int b = 0; b < 64; b++)
        out[((size_t)b * TT + t) * 256 + v] = acc[b] + bo;
}

// ---------------- launch ----------------
extern "C" void kernel_launch(void* const* d_in, const int* in_sizes, int n_in,
                              void* d_out, int out_size)
{
    const float* ecc     = (const float*)d_in[0];
    const int*   cat     = (const int*)  d_in[1];
    const float* num     = (const float*)d_in[2];
    const int*   payload = (const int*)  d_in[3];
    const float* e0      = (const float*)d_in[4];
    const float* e1      = (const float*)d_in[5];
    const float* e2      = (const float*)d_in[6];
    const float* bemb    = (const float*)d_in[7];
    const float* Wih0    = (const float*)d_in[8];
    const float* Whh0    = (const float*)d_in[9];
    const float* bih0    = (const float*)d_in[10];
    const float* bhh0    = (const float*)d_in[11];
    const float* Wih1    = (const float*)d_in[12];
    const float* Whh1    = (const float*)d_in[13];
    const float* bih1    = (const float*)d_in[14];
    const float* bhh1    = (const float*)d_in[15];
    const float* Wout    = (const float*)d_in[16];
    const float* bout    = (const float*)d_in[17];
    float* out = (float*)d_out;

    // parallel precompute
    build_ctx<<<198, 256>>>(ecc, cat, num, e0, e1, e2);
    ctx_gates_k<<<64, 256>>>(Wih0, bih0, bhh0);
    proj_k<<<dim3(256, 8), 256>>>(Wih0, bemb);
    transpose_wout<<<dim3(16, 8), dim3(32, 32)>>>(Wout);
    gx0_assemble<<<dim3(32, TT), 256>>>(payload);

    // layer 0 recurrence (single persistent launch)
    reset_bar_k<<<1, 1>>>();
    lstm_seq<<<128, 256>>>(Whh0);

    // layer 1 input gates (parallel GEMM), then layer 1 recurrence
    gx1_k<<<dim3(64, TT), 256>>>(Wih1, bih1, bhh1);
    reset_bar_k<<<1, 1>>>();
    lstm_seq<<<128, 256>>>(Whh1);

    // output head
    out_k<<<TT, 256>>>(bout, out);
}